// round 17
// baseline (speedup 1.0000x reference)
#include <cuda_runtime.h>
#include <cuda_fp16.h>
#include <math.h>
#include <stdint.h>

#define NN   50000
#define NE   600000
#define NET  650000   // NE + NN self loops
#define HID  128
#define CAP  64       // per-node slot capacity (P(deg>64) ~ 1e-28, clamped)

// ---------------- device scratch (no allocations allowed) ----------------
__device__ int   g_is64;
__device__ int   g_deg[NN];
__device__ int   g_csrc[NN * CAP];                  // fixed-stride CSR slots
__device__ __align__(16) __half g_h16a[NN * HID];   // h double buffer A
__device__ __align__(16) __half g_h16b[NN * HID];   // h double buffer B
__device__ float g_ssrc[3][NN];
__device__ float g_sdst[3][NN];
// pre-transposed weights: [layer][n*K + k], fp16
__device__ __align__(16) __half g_wt[4][128 * 128];

__device__ __forceinline__ uint32_t smem_u32(const void* p) {
    uint32_t a;
    asm("{ .reg .u64 t; cvta.to.shared.u64 t, %1; cvt.u32.u64 %0, t; }"
        : "=r"(a) : "l"(p));
    return a;
}

#define LDSM_X4(r0, r1, r2, r3, addr)                                         \
    asm volatile("ldmatrix.sync.aligned.m8n8.x4.shared.b16 {%0,%1,%2,%3}, [%4];" \
                 : "=r"(r0), "=r"(r1), "=r"(r2), "=r"(r3) : "r"(addr))

__device__ __forceinline__ void cpasync16(uint32_t dst, const void* src) {
    asm volatile("cp.async.cg.shared.global [%0], [%1], 16;"
                 :: "r"(dst), "l"(src));
}
#define CPASYNC_COMMIT() asm volatile("cp.async.commit_group;" ::: "memory")
#define CPASYNC_WAIT()   asm volatile("cp.async.wait_group 0;" ::: "memory")

// decode edge i -> (src, dst) straight from edge_index (int64 or int32)
__device__ __forceinline__ void edge_decode(const void* ed, int i,
                                            int& s, int& d) {
    if (i < NE) {
        if (g_is64) {
            const long long* p = (const long long*)ed;
            s = (int)p[i];
            d = (int)p[NE + i];
        } else {
            const int* p = (const int*)ed;
            s = p[i];
            d = p[NE + i];
        }
    } else {
        s = d = i - NE;   // self loop
    }
}

// ---------------- weight prep: fp32 W[K,N] -> fp16 W^T[N,K] --------------
__global__ void k_prepw(const float* __restrict__ W0, const float* __restrict__ W1,
                        const float* __restrict__ W2, const float* __restrict__ W3) {
    int l = blockIdx.y;
    const int Ks[4] = {64, 128, 128, 128};
    const int Ns[4] = {128, 128, 128, 64};
    const float* W = (l == 0) ? W0 : (l == 1) ? W1 : (l == 2) ? W2 : W3;
    int K = Ks[l], N = Ns[l];
    int i = blockIdx.x * 256 + threadIdx.x;
    if (i >= K * N) return;
    int k = i / N, n = i % N;
    g_wt[l][n * K + k] = __float2half_rn(W[i]);
}

// ---------------- zero degree + edge dtype detection (fused) -------------
__global__ void k_zero_all(const unsigned* __restrict__ w) {
    int i = blockIdx.x * blockDim.x + threadIdx.x;
    if (i < NN) g_deg[i] = 0;
    if (blockIdx.x == 0) {
        __shared__ int nz;
        if (threadIdx.x == 0) nz = 0;
        __syncthreads();
        for (int j = threadIdx.x; j < 1024; j += blockDim.x)
            if (w[2 * j + 1] != 0u) atomicAdd(&nz, 1);
        __syncthreads();
        if (threadIdx.x == 0) g_is64 = (nz == 0) ? 1 : 0;
    }
}

// single-pass CSR: slot = atomicAdd(deg[d]); csrc[d*CAP+slot] = s
__global__ void k_filld(const void* __restrict__ ed) {
    int t = blockIdx.x * blockDim.x + threadIdx.x;
#pragma unroll
    for (int e = 0; e < 2; e++) {
        int i = t * 2 + e;
        if (i >= NET) return;
        int s, d;
        edge_decode(ed, i, s, d);
        int slot = atomicAdd(&g_deg[d], 1);
        if (slot < CAP) g_csrc[d * CAP + slot] = s;
    }
}

// ---------------- warp-mma helper (fp16 in, fp32 acc) --------------------
__device__ __forceinline__ void mma16816(float* c, uint32_t a0, uint32_t a1,
                                         uint32_t a2, uint32_t a3,
                                         uint32_t b0, uint32_t b1) {
    asm volatile(
        "mma.sync.aligned.m16n8k16.row.col.f32.f16.f16.f32 "
        "{%0,%1,%2,%3}, {%4,%5,%6,%7}, {%8,%9}, {%0,%1,%2,%3};"
        : "+f"(c[0]), "+f"(c[1]), "+f"(c[2]), "+f"(c[3])
        : "r"(a0), "r"(a1), "r"(a2), "r"(a3), "r"(b0), "r"(b1));
}

// warp-level GAT aggregation of one node -> float4 result per lane.
// lane covers features [lane*4, lane*4+4).
__device__ __forceinline__ float4 warp_agg_node(
    int node, int lane, const __half* __restrict__ h16,
    const float* __restrict__ ssrc, float sd, const float* __restrict__ bagg) {
    const unsigned FULL = 0xFFFFFFFFu;
    int deg = g_deg[node];
    deg = (deg < CAP) ? deg : CAP;
    int beg = node * CAP;

    int s0 = 0, s1 = 0;
    float e0 = -INFINITY, e1 = -INFINITY;
    if (lane < deg) {
        s0 = g_csrc[beg + lane];
        float t = ssrc[s0] + sd;
        e0 = (t > 0.f) ? t : 0.2f * t;
    }
    if (lane + 32 < deg) {
        s1 = g_csrc[beg + lane + 32];
        float t = ssrc[s1] + sd;
        e1 = (t > 0.f) ? t : 0.2f * t;
    }
    float m = fmaxf(e0, e1);
#pragma unroll
    for (int o = 16; o; o >>= 1) m = fmaxf(m, __shfl_xor_sync(FULL, m, o));
    float w0 = __expf(e0 - m);
    float w1 = __expf(e1 - m);
    float den = w0 + w1;
#pragma unroll
    for (int o = 16; o; o >>= 1) den += __shfl_xor_sync(FULL, den, o);
    float inv = 1.f / (den + 1e-16f);

    float4 acc = make_float4(0.f, 0.f, 0.f, 0.f);
    for (int i = 0; i < deg; i += 4) {
        float w[4];
        int   sv[4];
#pragma unroll
        for (int t = 0; t < 4; t++) {
            int idx = i + t;
            int ln = idx & 31;
            float wt_ = __shfl_sync(FULL, (idx < 32) ? w0 : w1, ln);
            int   sx  = __shfl_sync(FULL, (idx < 32) ? s0 : s1, ln);
            w[t]  = (idx < deg) ? wt_ : 0.f;
            sv[t] = sx;
        }
#pragma unroll
        for (int t = 0; t < 4; t++) {
            uint2 hv = *(const uint2*)(h16 + (size_t)sv[t] * HID + lane * 4);
            float2 f01 = __half22float2(*(__half2*)&hv.x);
            float2 f23 = __half22float2(*(__half2*)&hv.y);
            acc.x += w[t] * f01.x;
            acc.y += w[t] * f01.y;
            acc.z += w[t] * f23.x;
            acc.w += w[t] * f23.y;
        }
    }

    float4 b4 = *(const float4*)(bagg + lane * 4);
    float4 v;
    v.x = acc.x * inv + b4.x;
    v.y = acc.y * inv + b4.y;
    v.z = acc.z * inv + b4.z;
    v.w = acc.w * inv + b4.w;
    v.x = (v.x > 0.f) ? v.x : 0.01f * v.x;
    v.y = (v.y > 0.f) ? v.y : 0.01f * v.y;
    v.z = (v.z > 0.f) ? v.z : 0.01f * v.z;
    v.w = (v.w > 0.f) ? v.w : 0.01f * v.w;
    return v;
}

// ---------------- L0 GEMM: h = x(fp32) @ W0, fused scores ----------------
__global__ void __launch_bounds__(256)
k_mma0(const float* __restrict__ A, const __half* __restrict__ B_g,
       __half* __restrict__ H16, float* __restrict__ ssrc,
       float* __restrict__ sdst, const float* __restrict__ a_s,
       const float* __restrict__ a_d) {
    constexpr int K = 64, N = 128, KP = K + 8;
    constexpr int A_SZ = 128 * KP;
    constexpr int NB = N / 8;

    extern __shared__ __half sm[];
    __half* A16 = sm;
    __half* Bs  = sm + A_SZ;

    int tid  = threadIdx.x;
    int wid  = tid >> 5;
    int lane = tid & 31;
    int row0 = blockIdx.x * 128;

    {
        uint32_t bb = smem_u32(Bs);
#pragma unroll
        for (int it = 0; it < (N * K / 8) / 256; it++) {
            int g  = it * 256 + tid;
            int n  = g / (K / 8);
            int k0 = (g % (K / 8)) * 8;
            cpasync16(bb + (uint32_t)(n * KP + k0) * 2, B_g + (size_t)n * K + k0);
        }
        CPASYNC_COMMIT();
    }
#pragma unroll
    for (int it = 0; it < (128 * K / 4) / 256; it++) {
        int g   = it * 256 + tid;
        int row = g / (K / 4);
        int col = (g % (K / 4)) * 4;
        float4 v = make_float4(0.f, 0.f, 0.f, 0.f);
        if (row0 + row < NN)
            v = *(const float4*)(A + (size_t)(row0 + row) * K + col);
        __half2 h01 = __floats2half2_rn(v.x, v.y);
        __half2 h23 = __floats2half2_rn(v.z, v.w);
        uint2 hv;
        hv.x = *(uint32_t*)&h01; hv.y = *(uint32_t*)&h23;
        *(uint2*)&A16[row * KP + col] = hv;
    }
    CPASYNC_WAIT();
    __syncthreads();

    float acc[NB][4];
#pragma unroll
    for (int nb = 0; nb < NB; nb++)
#pragma unroll
        for (int j = 0; j < 4; j++) acc[nb][j] = 0.f;

    uint32_t laneA = ((uint32_t)(wid * 16 + (lane & 15)) * KP +
                      ((lane >> 4) << 3)) * 2;
    uint32_t laneB = ((uint32_t)((lane & 7) + ((lane >> 4) << 3)) * KP +
                      (lane & 8)) * 2;
    uint32_t addrA = smem_u32(A16) + laneA;
    uint32_t addrB = smem_u32(Bs) + laneB;

#pragma unroll
    for (int ks = 0; ks < K / 16; ks++) {
        uint32_t bf[NB][2];
#pragma unroll
        for (int np = 0; np < NB / 2; np++) {
            LDSM_X4(bf[2 * np][0], bf[2 * np][1], bf[2 * np + 1][0],
                    bf[2 * np + 1][1],
                    addrB + (uint32_t)((np * 16 * KP + ks * 16) * 2));
        }
        uint32_t a0, a1, a2, a3;
        LDSM_X4(a0, a1, a2, a3, addrA + (uint32_t)(ks * 32));
#pragma unroll
        for (int nb = 0; nb < NB; nb++)
            mma16816(acc[nb], a0, a1, a2, a3, bf[nb][0], bf[nb][1]);
    }

    int gr0 = row0 + wid * 16 + (lane >> 2);
    int gr1 = gr0 + 8;
    int cbase = (lane & 3) * 2;
    float ps0 = 0.f, pd0 = 0.f, ps1 = 0.f, pd1 = 0.f;
#pragma unroll
    for (int nb = 0; nb < NB; nb++) {
        int c = nb * 8 + cbase;
        float s0 = a_s[c], s1 = a_s[c + 1];
        float d0 = a_d[c], d1 = a_d[c + 1];
        ps0 += acc[nb][0] * s0 + acc[nb][1] * s1;
        pd0 += acc[nb][0] * d0 + acc[nb][1] * d1;
        ps1 += acc[nb][2] * s0 + acc[nb][3] * s1;
        pd1 += acc[nb][2] * d0 + acc[nb][3] * d1;
        if (gr0 < NN)
            *(__half2*)(H16 + (size_t)gr0 * N + c) =
                __floats2half2_rn(acc[nb][0], acc[nb][1]);
        if (gr1 < NN)
            *(__half2*)(H16 + (size_t)gr1 * N + c) =
                __floats2half2_rn(acc[nb][2], acc[nb][3]);
    }
#pragma unroll
    for (int off = 1; off <= 2; off <<= 1) {
        ps0 += __shfl_xor_sync(0xFFFFFFFFu, ps0, off);
        pd0 += __shfl_xor_sync(0xFFFFFFFFu, pd0, off);
        ps1 += __shfl_xor_sync(0xFFFFFFFFu, ps1, off);
        pd1 += __shfl_xor_sync(0xFFFFFFFFu, pd1, off);
    }
    if ((lane & 3) == 0) {
        if (gr0 < NN) { ssrc[gr0] = ps0; sdst[gr0] = pd0; }
        if (gr1 < NN) { ssrc[gr1] = ps1; sdst[gr1] = pd1; }
    }
}

// ---------------- fused agg_L + GEMM_{L+1} -------------------------------
// Each warp aggregates its 16 A-tile rows straight into smem (fp16), then
// the block runs the mma sweep. K=128 always.
template <int N, bool SCORES, bool FINAL>
__global__ void __launch_bounds__(256)
k_fag(const __half* __restrict__ Hsrc, const float* __restrict__ bagg,
      const float* __restrict__ ssrc_in, const float* __restrict__ sdst_in,
      const __half* __restrict__ B_g,
      __half* __restrict__ Hout, float* __restrict__ ssrc_out,
      float* __restrict__ sdst_out,
      const float* __restrict__ a_s, const float* __restrict__ a_d,
      float* __restrict__ C, const float* __restrict__ bias_fin) {
    constexpr int K = 128, KP = K + 8;
    constexpr int A_SZ = 128 * KP;
    constexpr int NB = N / 8;

    extern __shared__ __half sm[];
    __half* A16 = sm;
    __half* Bs  = sm + A_SZ;

    int tid  = threadIdx.x;
    int wid  = tid >> 5;
    int lane = tid & 31;
    int row0 = blockIdx.x * 128;

    // stage B (W^T) via cp.async; overlaps the aggregation phase
    {
        uint32_t bb = smem_u32(Bs);
#pragma unroll
        for (int it = 0; it < (N * K / 8) / 256; it++) {
            int g  = it * 256 + tid;
            int n  = g / (K / 8);
            int k0 = (g % (K / 8)) * 8;
            cpasync16(bb + (uint32_t)(n * KP + k0) * 2, B_g + (size_t)n * K + k0);
        }
        CPASYNC_COMMIT();
    }

    // aggregation phase: warp owns A16 rows [wid*16, wid*16+16)
    for (int r = 0; r < 16; r++) {
        int local = wid * 16 + r;
        int node = row0 + local;
        if (node < NN) {
            float4 v = warp_agg_node(node, lane, Hsrc, ssrc_in,
                                     sdst_in[node], bagg);
            __half2 o01 = __floats2half2_rn(v.x, v.y);
            __half2 o23 = __floats2half2_rn(v.z, v.w);
            uint2 st;
            st.x = *(uint32_t*)&o01;
            st.y = *(uint32_t*)&o23;
            *(uint2*)&A16[local * KP + lane * 4] = st;
        }
    }
    CPASYNC_WAIT();
    __syncthreads();

    float acc[NB][4];
#pragma unroll
    for (int nb = 0; nb < NB; nb++)
#pragma unroll
        for (int j = 0; j < 4; j++) acc[nb][j] = 0.f;

    uint32_t laneA = ((uint32_t)(wid * 16 + (lane & 15)) * KP +
                      ((lane >> 4) << 3)) * 2;
    uint32_t laneB = ((uint32_t)((lane & 7) + ((lane >> 4) << 3)) * KP +
                      (lane & 8)) * 2;
    uint32_t addrA = smem_u32(A16) + laneA;
    uint32_t addrB = smem_u32(Bs) + laneB;

#pragma unroll
    for (int ks = 0; ks < K / 16; ks++) {
        uint32_t bf[NB][2];
#pragma unroll
        for (int np = 0; np < NB / 2; np++) {
            LDSM_X4(bf[2 * np][0], bf[2 * np][1], bf[2 * np + 1][0],
                    bf[2 * np + 1][1],
                    addrB + (uint32_t)((np * 16 * KP + ks * 16) * 2));
        }
        uint32_t a0, a1, a2, a3;
        LDSM_X4(a0, a1, a2, a3, addrA + (uint32_t)(ks * 32));
#pragma unroll
        for (int nb = 0; nb < NB; nb++)
            mma16816(acc[nb], a0, a1, a2, a3, bf[nb][0], bf[nb][1]);
    }

    // epilogue
    int gr0 = row0 + wid * 16 + (lane >> 2);
    int gr1 = gr0 + 8;
    int cbase = (lane & 3) * 2;
    float ps0 = 0.f, pd0 = 0.f, ps1 = 0.f, pd1 = 0.f;

#pragma unroll
    for (int nb = 0; nb < NB; nb++) {
        int c = nb * 8 + cbase;
        if (SCORES) {
            float s0 = a_s[c], s1 = a_s[c + 1];
            float d0 = a_d[c], d1 = a_d[c + 1];
            ps0 += acc[nb][0] * s0 + acc[nb][1] * s1;
            pd0 += acc[nb][0] * d0 + acc[nb][1] * d1;
            ps1 += acc[nb][2] * s0 + acc[nb][3] * s1;
            pd1 += acc[nb][2] * d0 + acc[nb][3] * d1;
            if (gr0 < NN)
                *(__half2*)(Hout + (size_t)gr0 * N + c) =
                    __floats2half2_rn(acc[nb][0], acc[nb][1]);
            if (gr1 < NN)
                *(__half2*)(Hout + (size_t)gr1 * N + c) =
                    __floats2half2_rn(acc[nb][2], acc[nb][3]);
        } else {
            float bx = 0.f, by = 0.f;
            if (FINAL) { bx = bias_fin[c]; by = bias_fin[c + 1]; }
            if (gr0 < NN)
                *(float2*)(C + (size_t)gr0 * N + c) =
                    make_float2(acc[nb][0] + bx, acc[nb][1] + by);
            if (gr1 < NN)
                *(float2*)(C + (size_t)gr1 * N + c) =
                    make_float2(acc[nb][2] + bx, acc[nb][3] + by);
        }
    }

    if (SCORES) {
#pragma unroll
        for (int off = 1; off <= 2; off <<= 1) {
            ps0 += __shfl_xor_sync(0xFFFFFFFFu, ps0, off);
            pd0 += __shfl_xor_sync(0xFFFFFFFFu, pd0, off);
            ps1 += __shfl_xor_sync(0xFFFFFFFFu, ps1, off);
            pd1 += __shfl_xor_sync(0xFFFFFFFFu, pd1, off);
        }
        if ((lane & 3) == 0) {
            if (gr0 < NN) { ssrc_out[gr0] = ps0; sdst_out[gr0] = pd0; }
            if (gr1 < NN) { ssrc_out[gr1] = ps1; sdst_out[gr1] = pd1; }
        }
    }
}

// ---------------- launch -------------------------------------------------
static cudaStream_t s_side = nullptr;
static cudaEvent_t  s_evFork = nullptr, s_evJoin = nullptr;

extern "C" void kernel_launch(void* const* d_in, const int* in_sizes, int n_in,
                              void* d_out, int out_size) {
    (void)in_sizes; (void)n_in; (void)out_size;

    if (!s_side) {
        cudaStreamCreateWithFlags(&s_side, cudaStreamNonBlocking);
        cudaEventCreateWithFlags(&s_evFork, cudaEventDisableTiming);
        cudaEventCreateWithFlags(&s_evJoin, cudaEventDisableTiming);
    }

    const float* x    = (const float*)d_in[0];
    const void*  eidx = d_in[1];

    float *p_ss, *p_sd;
    __half *p_ha, *p_hb, *p_wt;
    cudaGetSymbolAddress((void**)&p_ha, g_h16a);
    cudaGetSymbolAddress((void**)&p_hb, g_h16b);
    cudaGetSymbolAddress((void**)&p_ss, g_ssrc);
    cudaGetSymbolAddress((void**)&p_sd, g_sdst);
    cudaGetSymbolAddress((void**)&p_wt, g_wt);

    // dynamic smem (fp16 units -> bytes)
    const int SZ_L0   = (128 * 72 + 128 * 72) * 2;     // 36864
    const int SZ_MID  = (128 * 136 + 128 * 136) * 2;   // 69632
    const int SZ_FIN  = (128 * 136 + 64 * 136) * 2;    // 52224
    cudaFuncSetAttribute(k_mma0,
                         cudaFuncAttributeMaxDynamicSharedMemorySize, SZ_L0);
    cudaFuncSetAttribute(k_fag<128, true, false>,
                         cudaFuncAttributeMaxDynamicSharedMemorySize, SZ_MID);
    cudaFuncSetAttribute(k_fag<64, false, true>,
                         cudaFuncAttributeMaxDynamicSharedMemorySize, SZ_FIN);

    const int gridM = (NN + 127) / 128;        // 391

    // ---- fork: CSR chain on side stream ----
    cudaEventRecord(s_evFork, 0);
    cudaStreamWaitEvent(s_side, s_evFork, 0);
    k_zero_all<<<(NN + 255) / 256, 256, 0, s_side>>>((const unsigned*)eidx);
    k_filld<<<(NET / 2 + 255) / 256, 256, 0, s_side>>>(eidx);
    cudaEventRecord(s_evJoin, s_side);

    // ---- main: weight prep + layer-0 GEMM (independent of CSR) ----
    k_prepw<<<dim3(64, 4), 256>>>((const float*)d_in[2], (const float*)d_in[6],
                                  (const float*)d_in[10], (const float*)d_in[14]);
    k_mma0<<<gridM, 256, SZ_L0>>>(x, p_wt, p_ha, p_ss, p_sd,
                                  (const float*)d_in[3], (const float*)d_in[4]);

    // ---- join: fused agg+mma needs CSR ----
    cudaStreamWaitEvent(0, s_evJoin, 0);

    // fused agg0 + mma1: h_a -> h_b, scores layer1
    k_fag<128, true, false><<<gridM, 256, SZ_MID>>>(
        p_ha, (const float*)d_in[5], p_ss, p_sd,
        p_wt + (size_t)1 * 128 * 128,
        p_hb, p_ss + NN, p_sd + NN,
        (const float*)d_in[7], (const float*)d_in[8], nullptr, nullptr);

    // fused agg1 + mma2: h_b -> h_a, scores layer2
    k_fag<128, true, false><<<gridM, 256, SZ_MID>>>(
        p_hb, (const float*)d_in[9], p_ss + NN, p_sd + NN,
        p_wt + (size_t)2 * 128 * 128,
        p_ha, p_ss + 2 * NN, p_sd + 2 * NN,
        (const float*)d_in[11], (const float*)d_in[12], nullptr, nullptr);

    // fused agg2 + final GEMM: h_a -> d_out
    k_fag<64, false, true><<<gridM, 256, SZ_FIN>>>(
        p_ha, (const float*)d_in[13], p_ss + 2 * NN, p_sd + 2 * NN,
        p_wt + (size_t)3 * 128 * 128,
        nullptr, nullptr, nullptr, nullptr, nullptr,
        (float*)d_out, (const float*)d_in[15]);
}